// round 15
// baseline (speedup 1.0000x reference)
#include <cuda_runtime.h>
#include <cuda_fp16.h>
#include <cstdint>

#define HID 128
#define NN 50000
#define NE 800000
// byte strides (all ≡16 mod 128 -> ldmatrix conflict-free)
#define SA_STR 272   // A tiles rows: 136 halves
#define EF_STR 144   // ef tile rows: 72 halves
#define SB_STR 144   // B K=64 chunk buffers

extern __shared__ char dyn_smem[];

// ---------------- device scratch (allocation-free rule) ----------------
__device__ __half g_h[(size_t)NN * HID];
__device__ float  g_agg[(size_t)NN * HID];
__device__ __half g_nWt[128 * 128];
__device__ __half g_W1t[128 * 256];   // msg_W1^T [n][k]
__device__ __half g_W1et[128 * 64];   // (eW @ W1b)^T [n][kf]  (fused)
__device__ float  g_b1p[128];         // b1 + eb @ W1b
__device__ __half g_W2t[128 * 128];
__device__ __half g_U1t[128 * 256];
__device__ __half g_U2t[128 * 128];

// ======================= helpers (generic PTX) =========================
__device__ __forceinline__ uint32_t smem_u32(const void* p) {
    uint32_t a;
    asm("{ .reg .u64 t; cvta.to.shared.u64 t, %1; cvt.u32.u64 %0, t; }"
        : "=r"(a) : "l"(p));
    return a;
}
__device__ __forceinline__ void ldsm4(uint32_t r[4], uint32_t addr) {
    asm volatile("ldmatrix.sync.aligned.m8n8.x4.shared.b16 {%0,%1,%2,%3}, [%4];"
                 : "=r"(r[0]), "=r"(r[1]), "=r"(r[2]), "=r"(r[3]) : "r"(addr));
}
__device__ __forceinline__ void mma16(float c[4], const uint32_t a[4],
                                      uint32_t b0, uint32_t b1) {
    asm volatile("mma.sync.aligned.m16n8k16.row.col.f32.f16.f16.f32 "
                 "{%0,%1,%2,%3}, {%4,%5,%6,%7}, {%8,%9}, {%0,%1,%2,%3};"
                 : "+f"(c[0]), "+f"(c[1]), "+f"(c[2]), "+f"(c[3])
                 : "r"(a[0]), "r"(a[1]), "r"(a[2]), "r"(a[3]), "r"(b0), "r"(b1));
}
#define CP16(dst, src) \
    asm volatile("cp.async.cg.shared.global [%0], [%1], 16;" :: "r"(dst), "l"(src))
#define CP_COMMIT() asm volatile("cp.async.commit_group;" ::: "memory")
#define CP_WAIT(n)  asm volatile("cp.async.wait_group %0;" :: "n"(n) : "memory")

__device__ __forceinline__ uint32_t a_off(int lane, int strideB) {
    int row = (lane & 7) + ((lane & 8) ? 8 : 0);
    return (uint32_t)row * strideB + ((lane & 16) ? 16 : 0);
}
__device__ __forceinline__ uint32_t b_off(int lane, int strideB) {
    int row = (lane & 7) + ((lane & 16) ? 8 : 0);
    return (uint32_t)row * strideB + ((lane & 8) ? 16 : 0);
}

// ---- 64x32 warp GEMM (4 m16-tiles x 4 n8-cols) ----
__device__ __forceinline__ void zacc64(float acc[4][4][4]) {
#pragma unroll
    for (int m = 0; m < 4; ++m)
#pragma unroll
        for (int j = 0; j < 4; ++j)
#pragma unroll
            for (int k = 0; k < 4; ++k) acc[m][j][k] = 0.f;
}
template <int KSTEPS>
__device__ __forceinline__ void wgemm64(const uint32_t aA[4], const uint32_t bA[2],
                                        float acc[4][4][4]) {
#pragma unroll
    for (int ks = 0; ks < KSTEPS; ++ks) {
        uint32_t b0[4], b1[4];
        ldsm4(b0, bA[0] + ks * 32);
        ldsm4(b1, bA[1] + ks * 32);
#pragma unroll
        for (int m = 0; m < 4; ++m) {
            uint32_t a[4];
            ldsm4(a, aA[m] + ks * 32);
            mma16(acc[m][0], a, b0[0], b0[1]);
            mma16(acc[m][1], a, b0[2], b0[3]);
            mma16(acc[m][2], a, b1[0], b1[1]);
            mma16(acc[m][3], a, b1[2], b1[3]);
        }
    }
}

// ---- 32x32 warp GEMM (k_node @512 thr) ----
__device__ __forceinline__ void zacc(float acc[2][4][4]) {
#pragma unroll
    for (int i = 0; i < 2; ++i)
#pragma unroll
        for (int j = 0; j < 4; ++j)
#pragma unroll
            for (int k = 0; k < 4; ++k) acc[i][j][k] = 0.f;
}
template <int KSTEPS>
__device__ __forceinline__ void wgemm(uint32_t aA0, uint32_t aA1,
                                      const uint32_t bA[2], float acc[2][4][4]) {
#pragma unroll
    for (int ks = 0; ks < KSTEPS; ++ks) {
        uint32_t a0[4], a1[4];
        ldsm4(a0, aA0 + ks * 32);
        ldsm4(a1, aA1 + ks * 32);
#pragma unroll
        for (int jj = 0; jj < 2; ++jj) {
            uint32_t b[4];
            ldsm4(b, bA[jj] + ks * 32);
            mma16(acc[0][2 * jj],     a0, b[0], b[1]);
            mma16(acc[0][2 * jj + 1], a0, b[2], b[3]);
            mma16(acc[1][2 * jj],     a1, b[0], b[1]);
            mma16(acc[1][2 * jj + 1], a1, b[2], b[3]);
        }
    }
}

__device__ __forceinline__ void stage_chunk256(uint32_t dstB, const __half* srcBase,
                                               int srcK, int tid) {
#pragma unroll
    for (int i = tid; i < 128 * 8; i += 256) {
        int n = i >> 3, k8 = (i & 7) * 8;
        CP16(dstB + (uint32_t)(n * SB_STR + k8 * 2),
             srcBase + (size_t)n * srcK + k8);
    }
}

// ---------------------------------------------------------------------------
// Prep: transposes + fp16 + the eW@W1b fusion
// ---------------------------------------------------------------------------
__global__ void k_tW(const float* __restrict__ nW, const float* __restrict__ eW,
                     const float* __restrict__ eb, const float* __restrict__ W1,
                     const float* __restrict__ b1, const float* __restrict__ W2,
                     const float* __restrict__ U1, const float* __restrict__ U2) {
    int t = blockIdx.x * blockDim.x + threadIdx.x;
    int tot = gridDim.x * blockDim.x;
    for (int i = t; i < 128 * 128; i += tot) {
        int n = i >> 7, k = i & 127;
        g_nWt[i] = __float2half_rn(nW[k * 128 + n]);
        g_W2t[i] = __float2half_rn(W2[k * 128 + n]);
        g_U2t[i] = __float2half_rn(U2[k * 128 + n]);
    }
    for (int i = t; i < 128 * 256; i += tot) {
        int n = i >> 8, k = i & 255;
        g_W1t[i] = __float2half_rn(W1[k * 128 + n]);
        g_U1t[i] = __float2half_rn(U1[k * 128 + n]);
    }
    for (int i = t; i < 128 * 64; i += tot) {
        int n = i >> 6, kf = i & 63;
        float s = 0.f;
#pragma unroll 4
        for (int j = 0; j < 128; ++j)
            s = fmaf(eW[kf * 128 + j], W1[(128 + j) * 128 + n], s);
        g_W1et[i] = __float2half_rn(s);
    }
    for (int i = t; i < 128; i += tot) {
        float s = b1[i];
#pragma unroll 4
        for (int j = 0; j < 128; ++j)
            s = fmaf(eb[j], W1[(128 + j) * 128 + i], s);
        g_b1p[i] = s;
    }
}

__global__ __launch_bounds__(256) void k_zero_agg() {
    size_t i = (size_t)blockIdx.x * 256 + threadIdx.x;
    reinterpret_cast<float4*>(g_agg)[i] = make_float4(0.f, 0.f, 0.f, 0.f);
}

// ---------------------------------------------------------------------------
// Kernel 1: h = fp16(node_feats @ node_W + node_b) -> g_h   (512 thr)
// ---------------------------------------------------------------------------
static constexpr int NODE_SA = 0;
static constexpr int NODE_SB = 128 * SA_STR;
static constexpr int NODE_BIAS = NODE_SB + 128 * SA_STR;
static constexpr int NODE_SMEM = NODE_BIAS + 512;

__global__ __launch_bounds__(512, 1) void k_node(const float* __restrict__ nf,
                                                 const float* __restrict__ b) {
    char* smem = dyn_smem;
    float* sBias = reinterpret_cast<float*>(smem + NODE_BIAS);
    const uint32_t sb0 = smem_u32(smem);
    const int tid = threadIdx.x, lane = tid & 31, w = tid >> 5;
    const int base = blockIdx.x * 128;

    if (tid < 128) sBias[tid] = b[tid];
    for (int i = tid; i < 128 * 32; i += 512) {
        int r = i >> 5, c = (i & 31) * 4;
        int gr = base + r;
        float4 v = make_float4(0.f, 0.f, 0.f, 0.f);
        if (gr < NN) v = *reinterpret_cast<const float4*>(nf + (size_t)gr * HID + c);
        __half2* p = reinterpret_cast<__half2*>(smem + NODE_SA + r * SA_STR + c * 2);
        p[0] = __floats2half2_rn(v.x, v.y);
        p[1] = __floats2half2_rn(v.z, v.w);
    }
    for (int i = tid; i < 128 * 16; i += 512) {
        int r = i >> 4, s = (i & 15);
        *reinterpret_cast<float4*>(smem + NODE_SB + r * SA_STR + s * 16) =
            *reinterpret_cast<const float4*>(
                reinterpret_cast<const char*>(g_nWt) + (size_t)r * 256 + s * 16);
    }
    __syncthreads();

    const int mb = (w & 3) * 32, nb = (w >> 2) * 32;
    uint32_t aA0 = sb0 + NODE_SA + (uint32_t)mb * SA_STR + a_off(lane, SA_STR);
    uint32_t aA1 = aA0 + 16 * SA_STR;
    uint32_t bA[2];
#pragma unroll
    for (int jj = 0; jj < 2; ++jj)
        bA[jj] = sb0 + NODE_SB + (uint32_t)(nb + jj * 16) * SA_STR + b_off(lane, SA_STR);

    float acc[2][4][4];
    zacc(acc);
    wgemm<8>(aA0, aA1, bA, acc);

    const int g = lane >> 2, tg = lane & 3;
#pragma unroll
    for (int i = 0; i < 2; ++i) {
        int r0 = base + mb + i * 16 + g;
#pragma unroll
        for (int j = 0; j < 4; ++j) {
            int c = nb + j * 8 + 2 * tg;
            if (r0 < NN)
                *reinterpret_cast<__half2*>(g_h + (size_t)r0 * HID + c) =
                    __floats2half2_rn(acc[i][j][0] + sBias[c], acc[i][j][1] + sBias[c + 1]);
            if (r0 + 8 < NN)
                *reinterpret_cast<__half2*>(g_h + (size_t)(r0 + 8) * HID + c) =
                    __floats2half2_rn(acc[i][j][2] + sBias[c], acc[i][j][3] + sBias[c + 1]);
        }
    }
}

// ---------------------------------------------------------------------------
// Kernel 2: fused edge pipeline, triple-buffered weight chunks.
//   t = relu(h@W1a + ef@W1e + b1') ; m = t@W2 + b2 ; scatter-add.
// 256 threads, 2 CTAs/SM, 64x32 warp tiles.
// smem: sH | sEF | B0 | B1 | B2 | misc = 110080 B
// ---------------------------------------------------------------------------
static constexpr int SH_B  = 0;
static constexpr int EF_B  = 34816;
static constexpr int B0_B  = EF_B + 128 * EF_STR;      // 53248
static constexpr int B1_B  = B0_B + 128 * SB_STR;      // 71680
static constexpr int B2_B  = B1_B + 128 * SB_STR;      // 90112
static constexpr int MISC_B = B2_B + 128 * SB_STR;     // 108544
static constexpr int EDGE_SMEM = MISC_B + 3 * 128 * 4; // 110080

__global__ __launch_bounds__(256, 2) void k_edge(const int* __restrict__ eidx,
                                                 const float* __restrict__ ef,
                                                 const float* __restrict__ b2) {
    char* smem = dyn_smem;
    float* sB1p = reinterpret_cast<float*>(smem + MISC_B);
    float* sB2b = sB1p + 128;
    int* sDst = reinterpret_cast<int*>(sB2b + 128);
    const uint32_t sb0 = smem_u32(smem);

    const int tid = threadIdx.x, lane = tid & 31, w = tid >> 5;
    const int e0 = blockIdx.x * 128;

    if (tid < 128) {
        sDst[tid] = eidx[NE + e0 + tid];
        sB1p[tid] = g_b1p[tid];
    } else {
        sB2b[tid - 128] = b2[tid - 128];
    }

    // g0: gather h[src] -> sH
#pragma unroll
    for (int i = tid; i < 128 * 16; i += 256) {
        int r = i >> 4, s = i & 15;
        int src = eidx[e0 + r];
        CP16(sb0 + SH_B + (uint32_t)(r * SA_STR + s * 16),
             g_h + (size_t)src * HID + s * 8);
    }
    CP_COMMIT();
    // g1: c1 = W1a[:,0:64] -> B0
    stage_chunk256(sb0 + B0_B, g_W1t, 256, tid);
    CP_COMMIT();
    // g2: c2 = W1a[:,64:128] -> B1
    stage_chunk256(sb0 + B1_B, g_W1t + 64, 256, tid);
    CP_COMMIT();
    // g3: c3 = W1e -> B2
    stage_chunk256(sb0 + B2_B, g_W1et, 64, tid);
    CP_COMMIT();

    // ef [128x64] fp32 -> fp16 into sEF
#pragma unroll
    for (int i = tid; i < 128 * 16; i += 256) {
        int r = i >> 4, c = (i & 15) * 4;
        float4 v = *reinterpret_cast<const float4*>(ef + (size_t)(e0 + r) * 64 + c);
        __half2* p = reinterpret_cast<__half2*>(smem + EF_B + r * EF_STR + c * 2);
        p[0] = __floats2half2_rn(v.x, v.y);
        p[1] = __floats2half2_rn(v.z, v.w);
    }

    // warp tiling: 2 (M) x 4 (N) warps, 64x32 each
    const int mb = (w & 1) * 64, nb = (w >> 1) * 32;
    uint32_t aH[4], aH2[4], aF[4];
#pragma unroll
    for (int m = 0; m < 4; ++m) {
        aH[m] = sb0 + SH_B + (uint32_t)(mb + m * 16) * SA_STR + a_off(lane, SA_STR);
        aH2[m] = aH[m] + 128;
        aF[m] = sb0 + EF_B + (uint32_t)(mb + m * 16) * EF_STR + a_off(lane, EF_STR);
    }
    uint32_t b0A[2], b1A[2], b2A[2];
#pragma unroll
    for (int jj = 0; jj < 2; ++jj) {
        uint32_t off = (uint32_t)(nb + jj * 16) * SB_STR + b_off(lane, SB_STR);
        b0A[jj] = sb0 + B0_B + off;
        b1A[jj] = sb0 + B1_B + off;
        b2A[jj] = sb0 + B2_B + off;
    }

    const int g = lane >> 2, tg = lane & 3;
    float acc[4][4][4];

    // ---- GEMM1: t_acc = h@W1a + ef@W1e ----
    CP_WAIT(2);          // g0 (gather) + g1 (c1) complete
    __syncthreads();     // publish sH, c1, ef, biases
    zacc64(acc);
    wgemm64<4>(aH, b0A, acc);                       // c1: h k0:64

    CP_WAIT(0);          // c2, c3 complete
    __syncthreads();     // publish c2, c3; B0 consumed by all
    stage_chunk256(sb0 + B0_B, g_W2t, 128, tid);    // c4 = W2[:,0:64] -> B0
    CP_COMMIT();
    wgemm64<4>(aH2, b1A, acc);                      // c2: h k64:128
    wgemm64<4>(aF, b2A, acc);                       // c3: ef @ W1e (uninterrupted)

    CP_WAIT(0);
    __syncthreads();     // publish c4; B1,B2 free; all h reads done
    stage_chunk256(sb0 + B1_B, g_W2t + 64, 128, tid);  // c5 = W2[:,64:128] -> B1
    CP_COMMIT();

    // epilogue: t = relu(acc + b1') -> sH
#pragma unroll
    for (int m = 0; m < 4; ++m) {
        int r0 = mb + m * 16 + g;
#pragma unroll
        for (int j = 0; j < 4; ++j) {
            int c = nb + j * 8 + 2 * tg;
            *reinterpret_cast<__half2*>(smem + SH_B + r0 * SA_STR + c * 2) =
                __floats2half2_rn(fmaxf(acc[m][j][0] + sB1p[c], 0.f),
                                  fmaxf(acc[m][j][1] + sB1p[c + 1], 0.f));
            *reinterpret_cast<__half2*>(smem + SH_B + (r0 + 8) * SA_STR + c * 2) =
                __floats2half2_rn(fmaxf(acc[m][j][2] + sB1p[c], 0.f),
                                  fmaxf(acc[m][j][3] + sB1p[c + 1], 0.f));
        }
    }
    CP_WAIT(0);          // c5 landed (own copies)
    __syncthreads();     // publish t + c5

    // ---- GEMM2: m = t @ W2 (K=128, uninterrupted) ----
    zacc64(acc);
    wgemm64<4>(aH, b0A, acc);                       // c4: t k0:64
    wgemm64<4>(aH2, b1A, acc);                      // c5: t k64:128

    // scalar-atomic scatter into g_agg[dst]
#pragma unroll
    for (int m = 0; m < 4; ++m) {
        int r0 = mb + m * 16 + g;
        float* p0 = g_agg + (size_t)sDst[r0] * HID;
        float* p1 = g_agg + (size_t)sDst[r0 + 8] * HID;
#pragma unroll
        for (int j = 0; j < 4; ++j) {
            int c = nb + j * 8 + 2 * tg;
            atomicAdd(p0 + c, acc[m][j][0] + sB2b[c]);
            atomicAdd(p0 + c + 1, acc[m][j][1] + sB2b[c + 1]);
            atomicAdd(p1 + c, acc[m][j][2] + sB2b[c]);
            atomicAdd(p1 + c + 1, acc[m][j][3] + sB2b[c + 1]);
        }
    }
}

// ---------------------------------------------------------------------------
// Kernel 3: out = relu([nf|agg] @ U1 + ub1) @ U2 + ub2
// 256 threads, 2 CTAs/SM, 64x32 warp tiles, 6 streamed K=64 chunks.
// smem: sNF | sAG | B0 | B1 | misc = 107520 B
// ---------------------------------------------------------------------------
static constexpr int UNF_B = 0;
static constexpr int UAG_B = 34816;
static constexpr int UB0_B = UAG_B + 128 * SA_STR;     // 69632
static constexpr int UB1_B = UB0_B + 128 * SB_STR;     // 88064
static constexpr int UMISC_B = UB1_B + 128 * SB_STR;   // 106496
static constexpr int UPD_SMEM = UMISC_B + 2 * 128 * 4; // 107520

__global__ __launch_bounds__(256, 2) void k_update(const float* __restrict__ nf,
                                                   const float* __restrict__ b1,
                                                   const float* __restrict__ b2,
                                                   float* __restrict__ out) {
    char* smem = dyn_smem;
    float* sB1 = reinterpret_cast<float*>(smem + UMISC_B);
    float* sB2 = sB1 + 128;
    const uint32_t sb0 = smem_u32(smem);

    const int tid = threadIdx.x, lane = tid & 31, w = tid >> 5;
    const int base = blockIdx.x * 128;

    if (tid < 128) sB1[tid] = b1[tid];
    else sB2[tid - 128] = b2[tid - 128];

    // u1, u2 = U1[:,0:64], U1[:,64:128]
    stage_chunk256(sb0 + UB0_B, g_U1t, 256, tid);
    CP_COMMIT();
    stage_chunk256(sb0 + UB1_B, g_U1t + 64, 256, tid);
    CP_COMMIT();

    // A tiles: nf -> sNF, agg -> sAG (fp32 -> fp16, guarded)
    for (int i = tid; i < 128 * 32; i += 256) {
        int r = i >> 5, c = (i & 31) * 4;
        int gr = base + r;
        float4 v0 = make_float4(0.f, 0.f, 0.f, 0.f), v1 = v0;
        if (gr < NN) {
            v0 = *reinterpret_cast<const float4*>(nf + (size_t)gr * HID + c);
            v1 = *reinterpret_cast<const float4*>(g_agg + (size_t)gr * HID + c);
        }
        __half2* p0 = reinterpret_cast<__half2*>(smem + UNF_B + r * SA_STR + c * 2);
        p0[0] = __floats2half2_rn(v0.x, v0.y);
        p0[1] = __floats2half2_rn(v0.z, v0.w);
        __half2* p1 = reinterpret_cast<__half2*>(smem + UAG_B + r * SA_STR + c * 2);
        p1[0] = __floats2half2_rn(v1.x, v1.y);
        p1[1] = __floats2half2_rn(v1.z, v1.w);
    }

    const int mb = (w & 1) * 64, nb = (w >> 1) * 32;
    uint32_t aN[4], aN2[4], aG[4], aG2[4];
#pragma unroll
    for (int m = 0; m < 4; ++m) {
        aN[m] = sb0 + UNF_B + (uint32_t)(mb + m * 16) * SA_STR + a_off(lane, SA_STR);
        aN2[m] = aN[m] + 128;
        aG[m] = sb0 + UAG_B + (uint32_t)(mb + m * 16) * SA_STR + a_off(lane, SA_STR);
        aG2[m] = aG[m] + 128;
    }
    uint32_t b0A[2], b1A[2];
#pragma unroll
    for (int jj = 0; jj < 2; ++jj) {
        uint32_t off = (uint32_t)(nb + jj * 16) * SB_STR + b_off(lane, SB_STR);
        b0A[jj] = sb0 + UB0_B + off;
        b1A[jj] = sb0 + UB1_B + off;
    }

    const int g = lane >> 2, tg = lane & 3;
    float acc[4][4][4];

    CP_WAIT(0);
    __syncthreads();     // publish u1, u2, A tiles, biases
    zacc64(acc);
    wgemm64<4>(aN, b0A, acc);                       // u1: nf k0:64
    __syncthreads();     // B0 consumed by all (WAR)
    stage_chunk256(sb0 + UB0_B, g_U1t + 128, 256, tid);  // u3 -> B0
    CP_COMMIT();
    wgemm64<4>(aN2, b1A, acc);                      // u2: nf k64:128
    CP_WAIT(0);
    __syncthreads();     // publish u3; B1 free
    stage_chunk256(sb0 + UB1_B, g_U1t + 192, 256, tid);  // u4 -> B1
    CP_COMMIT();
    wgemm64<4>(aG, b0A, acc);                       // u3: agg k0:64
    CP_WAIT(0);
    __syncthreads();     // publish u4; B0 free
    stage_chunk256(sb0 + UB0_B, g_U2t, 128, tid);   // u5 = U2[:,0:64] -> B0
    CP_COMMIT();
    wgemm64<4>(aG2, b1A, acc);                      // u4: agg k64:128
    CP_WAIT(0);
    __syncthreads();     // publish u5; B1 free
    stage_chunk256(sb0 + UB1_B, g_U2t + 64, 128, tid);  // u6 -> B1
    CP_COMMIT();

    // epilogue: t = relu(acc + b1) -> sNF  (nf reads done at u2 + synced)
#pragma unroll
    for (int m = 0; m < 4; ++m) {
        int r0 = mb + m * 16 + g;
#pragma unroll
        for (int j = 0; j < 4; ++j) {
            int c = nb + j * 8 + 2 * tg;
            *reinterpret_cast<__half2*>(smem + UNF_B + r0 * SA_STR + c * 2) =
                __floats2half2_rn(fmaxf(acc[m][j][0] + sB1[c], 0.f),
                                  fmaxf(acc[m][j][1] + sB1[c + 1], 0.f));
            *reinterpret_cast<__half2*>(smem + UNF_B + (r0 + 8) * SA_STR + c * 2) =
                __floats2half2_rn(fmaxf(acc[m][j][2] + sB1[c], 0.f),
                                  fmaxf(acc[m][j][3] + sB1[c + 1], 0.f));
        }
    }
    CP_WAIT(0);          // u6 landed
    __syncthreads();     // publish t + u6

    // out = t @ U2 + b2  (K=128, uninterrupted)
    zacc64(acc);
    wgemm64<4>(aN, b0A, acc);                       // u5
    wgemm64<4>(aN2, b1A, acc);                      // u6

#pragma unroll
    for (int m = 0; m < 4; ++m) {
        int r0 = base + mb + m * 16 + g;
#pragma unroll
        for (int j = 0; j < 4; ++j) {
            int c = nb + j * 8 + 2 * tg;
            if (r0 < NN)
                *reinterpret_cast<float2*>(out + (size_t)r0 * HID + c) =
                    make_float2(acc[m][j][0] + sB2[c], acc[m][j][1] + sB2[c + 1]);
            if (r0 + 8 < NN)
                *reinterpret_cast<float2*>(out + (size_t)(r0 + 8) * HID + c) =
                    make_float2(acc[m][j][2] + sB2[c], acc[m][j][3] + sB2[c + 1]);
        }
    }
}

// ---------------------------------------------------------------------------
extern "C" void kernel_launch(void* const* d_in, const int* in_sizes, int n_in,
                              void* d_out, int out_size) {
    const float* node_feats = (const float*)d_in[0];
    const int*   edge_idx   = (const int*)d_in[1];
    const float* edge_feats = (const float*)d_in[2];
    const float* node_W     = (const float*)d_in[3];
    const float* node_b     = (const float*)d_in[4];
    const float* edge_W     = (const float*)d_in[5];
    const float* edge_b     = (const float*)d_in[6];
    const float* msg_W1     = (const float*)d_in[7];
    const float* msg_b1     = (const float*)d_in[8];
    const float* msg_W2     = (const float*)d_in[9];
    const float* msg_b2     = (const float*)d_in[10];
    const float* upd_W1     = (const float*)d_in[11];
    const float* upd_b1     = (const float*)d_in[12];
    const float* upd_W2     = (const float*)d_in[13];
    const float* upd_b2     = (const float*)d_in[14];
    float* out = (float*)d_out;

    cudaFuncSetAttribute(k_node,   cudaFuncAttributeMaxDynamicSharedMemorySize, NODE_SMEM);
    cudaFuncSetAttribute(k_edge,   cudaFuncAttributeMaxDynamicSharedMemorySize, EDGE_SMEM);
    cudaFuncSetAttribute(k_update, cudaFuncAttributeMaxDynamicSharedMemorySize, UPD_SMEM);

    const int NB_NODE = (NN + 127) / 128;  // 391
    const int NB_EDGE = NE / 128;          // 6250

    k_tW<<<128, 256>>>(node_W, edge_W, edge_b, msg_W1, msg_b1, msg_W2,
                       upd_W1, upd_W2);
    k_zero_agg<<<NN * HID / 4 / 256, 256>>>();
    k_node<<<NB_NODE, 512, NODE_SMEM>>>(node_feats, node_b);
    k_edge<<<NB_EDGE, 256, EDGE_SMEM>>>(edge_idx, edge_feats, msg_b2);
    k_update<<<NB_NODE, 256, UPD_SMEM>>>(node_feats, upd_b1, upd_b2, out);
}

// round 16
// speedup vs baseline: 1.0671x; 1.0671x over previous
#include <cuda_runtime.h>
#include <cuda_fp16.h>
#include <cstdint>

#define HID 128
#define NN 50000
#define NE 800000
// byte strides (all ≡16 mod 128 -> ldmatrix conflict-free)
#define SA_STR 272   // A tiles rows: 136 halves
#define EF_STR 144   // ef tile rows: 72 halves
#define SB_STR 144   // B K=64 chunk buffers

extern __shared__ char dyn_smem[];

// ---------------- device scratch (allocation-free rule) ----------------
__device__ __half g_h[(size_t)NN * HID];
__device__ float  g_agg[(size_t)NN * HID];
__device__ __half g_nWt[128 * 128];
__device__ __half g_W1t[128 * 256];   // msg_W1^T [n][k]
__device__ __half g_W1et[128 * 64];   // (eW @ W1b)^T [n][kf]  (fused)
__device__ float  g_b1p[128];         // b1 + eb @ W1b
__device__ __half g_W2t[128 * 128];
__device__ __half g_U1t[128 * 256];
__device__ __half g_U2t[128 * 128];

// ======================= helpers (generic PTX) =========================
__device__ __forceinline__ uint32_t smem_u32(const void* p) {
    uint32_t a;
    asm("{ .reg .u64 t; cvta.to.shared.u64 t, %1; cvt.u32.u64 %0, t; }"
        : "=r"(a) : "l"(p));
    return a;
}
__device__ __forceinline__ void ldsm4(uint32_t r[4], uint32_t addr) {
    asm volatile("ldmatrix.sync.aligned.m8n8.x4.shared.b16 {%0,%1,%2,%3}, [%4];"
                 : "=r"(r[0]), "=r"(r[1]), "=r"(r[2]), "=r"(r[3]) : "r"(addr));
}
__device__ __forceinline__ void mma16(float c[4], const uint32_t a[4],
                                      uint32_t b0, uint32_t b1) {
    asm volatile("mma.sync.aligned.m16n8k16.row.col.f32.f16.f16.f32 "
                 "{%0,%1,%2,%3}, {%4,%5,%6,%7}, {%8,%9}, {%0,%1,%2,%3};"
                 : "+f"(c[0]), "+f"(c[1]), "+f"(c[2]), "+f"(c[3])
                 : "r"(a[0]), "r"(a[1]), "r"(a[2]), "r"(a[3]), "r"(b0), "r"(b1));
}
#define CP16(dst, src) \
    asm volatile("cp.async.cg.shared.global [%0], [%1], 16;" :: "r"(dst), "l"(src))
#define CP_COMMIT() asm volatile("cp.async.commit_group;" ::: "memory")
#define CP_WAIT(n)  asm volatile("cp.async.wait_group %0;" :: "n"(n) : "memory")
// vectored global reduction (sm_90 base PTX)
#define RED_V2(gptr, x, y) \
    asm volatile("red.global.add.v2.f32 [%0], {%1, %2};" \
                 :: "l"(gptr), "f"(x), "f"(y) : "memory")

__device__ __forceinline__ uint32_t a_off(int lane, int strideB) {
    int row = (lane & 7) + ((lane & 8) ? 8 : 0);
    return (uint32_t)row * strideB + ((lane & 16) ? 16 : 0);
}
__device__ __forceinline__ uint32_t b_off(int lane, int strideB) {
    int row = (lane & 7) + ((lane & 16) ? 8 : 0);
    return (uint32_t)row * strideB + ((lane & 8) ? 16 : 0);
}

// ---- 64x32 warp GEMM (4 m16-tiles x 4 n8-cols) ----
__device__ __forceinline__ void zacc64(float acc[4][4][4]) {
#pragma unroll
    for (int m = 0; m < 4; ++m)
#pragma unroll
        for (int j = 0; j < 4; ++j)
#pragma unroll
            for (int k = 0; k < 4; ++k) acc[m][j][k] = 0.f;
}
template <int KSTEPS>
__device__ __forceinline__ void wgemm64(const uint32_t aA[4], const uint32_t bA[2],
                                        float acc[4][4][4]) {
#pragma unroll
    for (int ks = 0; ks < KSTEPS; ++ks) {
        uint32_t b0[4], b1[4];
        ldsm4(b0, bA[0] + ks * 32);
        ldsm4(b1, bA[1] + ks * 32);
#pragma unroll
        for (int m = 0; m < 4; ++m) {
            uint32_t a[4];
            ldsm4(a, aA[m] + ks * 32);
            mma16(acc[m][0], a, b0[0], b0[1]);
            mma16(acc[m][1], a, b0[2], b0[3]);
            mma16(acc[m][2], a, b1[0], b1[1]);
            mma16(acc[m][3], a, b1[2], b1[3]);
        }
    }
}

// ---- 32x32 warp GEMM (k_node @512 thr) ----
__device__ __forceinline__ void zacc(float acc[2][4][4]) {
#pragma unroll
    for (int i = 0; i < 2; ++i)
#pragma unroll
        for (int j = 0; j < 4; ++j)
#pragma unroll
            for (int k = 0; k < 4; ++k) acc[i][j][k] = 0.f;
}
template <int KSTEPS>
__device__ __forceinline__ void wgemm(uint32_t aA0, uint32_t aA1,
                                      const uint32_t bA[2], float acc[2][4][4]) {
#pragma unroll
    for (int ks = 0; ks < KSTEPS; ++ks) {
        uint32_t a0[4], a1[4];
        ldsm4(a0, aA0 + ks * 32);
        ldsm4(a1, aA1 + ks * 32);
#pragma unroll
        for (int jj = 0; jj < 2; ++jj) {
            uint32_t b[4];
            ldsm4(b, bA[jj] + ks * 32);
            mma16(acc[0][2 * jj],     a0, b[0], b[1]);
            mma16(acc[0][2 * jj + 1], a0, b[2], b[3]);
            mma16(acc[1][2 * jj],     a1, b[0], b[1]);
            mma16(acc[1][2 * jj + 1], a1, b[2], b[3]);
        }
    }
}

__device__ __forceinline__ void stage_chunk256(uint32_t dstB, const __half* srcBase,
                                               int srcK, int tid) {
#pragma unroll
    for (int i = tid; i < 128 * 8; i += 256) {
        int n = i >> 3, k8 = (i & 7) * 8;
        CP16(dstB + (uint32_t)(n * SB_STR + k8 * 2),
             srcBase + (size_t)n * srcK + k8);
    }
}

// ---------------------------------------------------------------------------
// Prep: transposes + fp16 + the eW@W1b fusion
// ---------------------------------------------------------------------------
__global__ void k_tW(const float* __restrict__ nW, const float* __restrict__ eW,
                     const float* __restrict__ eb, const float* __restrict__ W1,
                     const float* __restrict__ b1, const float* __restrict__ W2,
                     const float* __restrict__ U1, const float* __restrict__ U2) {
    int t = blockIdx.x * blockDim.x + threadIdx.x;
    int tot = gridDim.x * blockDim.x;
    for (int i = t; i < 128 * 128; i += tot) {
        int n = i >> 7, k = i & 127;
        g_nWt[i] = __float2half_rn(nW[k * 128 + n]);
        g_W2t[i] = __float2half_rn(W2[k * 128 + n]);
        g_U2t[i] = __float2half_rn(U2[k * 128 + n]);
    }
    for (int i = t; i < 128 * 256; i += tot) {
        int n = i >> 8, k = i & 255;
        g_W1t[i] = __float2half_rn(W1[k * 128 + n]);
        g_U1t[i] = __float2half_rn(U1[k * 128 + n]);
    }
    for (int i = t; i < 128 * 64; i += tot) {
        int n = i >> 6, kf = i & 63;
        float s = 0.f;
#pragma unroll 4
        for (int j = 0; j < 128; ++j)
            s = fmaf(eW[kf * 128 + j], W1[(128 + j) * 128 + n], s);
        g_W1et[i] = __float2half_rn(s);
    }
    for (int i = t; i < 128; i += tot) {
        float s = b1[i];
#pragma unroll 4
        for (int j = 0; j < 128; ++j)
            s = fmaf(eb[j], W1[(128 + j) * 128 + i], s);
        g_b1p[i] = s;
    }
}

// ---------------------------------------------------------------------------
// Kernel 1: h = fp16(node_feats @ node_W + node_b) -> g_h; also zeroes g_agg
// ---------------------------------------------------------------------------
static constexpr int NODE_SA = 0;
static constexpr int NODE_SB = 128 * SA_STR;
static constexpr int NODE_BIAS = NODE_SB + 128 * SA_STR;
static constexpr int NODE_SMEM = NODE_BIAS + 512;

__global__ __launch_bounds__(512, 1) void k_node(const float* __restrict__ nf,
                                                 const float* __restrict__ b) {
    char* smem = dyn_smem;
    float* sBias = reinterpret_cast<float*>(smem + NODE_BIAS);
    const uint32_t sb0 = smem_u32(smem);
    const int tid = threadIdx.x, lane = tid & 31, w = tid >> 5;
    const int base = blockIdx.x * 128;

    if (tid < 128) sBias[tid] = b[tid];
    // zero g_agg rows owned by this block (fused k_zero_agg)
    for (int i = tid; i < 128 * 32; i += 512) {
        int r = i >> 5, c = (i & 31) * 4;
        int gr = base + r;
        if (gr < NN)
            *reinterpret_cast<float4*>(g_agg + (size_t)gr * HID + c) =
                make_float4(0.f, 0.f, 0.f, 0.f);
    }
    for (int i = tid; i < 128 * 32; i += 512) {
        int r = i >> 5, c = (i & 31) * 4;
        int gr = base + r;
        float4 v = make_float4(0.f, 0.f, 0.f, 0.f);
        if (gr < NN) v = *reinterpret_cast<const float4*>(nf + (size_t)gr * HID + c);
        __half2* p = reinterpret_cast<__half2*>(smem + NODE_SA + r * SA_STR + c * 2);
        p[0] = __floats2half2_rn(v.x, v.y);
        p[1] = __floats2half2_rn(v.z, v.w);
    }
    for (int i = tid; i < 128 * 16; i += 512) {
        int r = i >> 4, s = (i & 15);
        *reinterpret_cast<float4*>(smem + NODE_SB + r * SA_STR + s * 16) =
            *reinterpret_cast<const float4*>(
                reinterpret_cast<const char*>(g_nWt) + (size_t)r * 256 + s * 16);
    }
    __syncthreads();

    const int mb = (w & 3) * 32, nb = (w >> 2) * 32;
    uint32_t aA0 = sb0 + NODE_SA + (uint32_t)mb * SA_STR + a_off(lane, SA_STR);
    uint32_t aA1 = aA0 + 16 * SA_STR;
    uint32_t bA[2];
#pragma unroll
    for (int jj = 0; jj < 2; ++jj)
        bA[jj] = sb0 + NODE_SB + (uint32_t)(nb + jj * 16) * SA_STR + b_off(lane, SA_STR);

    float acc[2][4][4];
    zacc(acc);
    wgemm<8>(aA0, aA1, bA, acc);

    const int g = lane >> 2, tg = lane & 3;
#pragma unroll
    for (int i = 0; i < 2; ++i) {
        int r0 = base + mb + i * 16 + g;
#pragma unroll
        for (int j = 0; j < 4; ++j) {
            int c = nb + j * 8 + 2 * tg;
            if (r0 < NN)
                *reinterpret_cast<__half2*>(g_h + (size_t)r0 * HID + c) =
                    __floats2half2_rn(acc[i][j][0] + sBias[c], acc[i][j][1] + sBias[c + 1]);
            if (r0 + 8 < NN)
                *reinterpret_cast<__half2*>(g_h + (size_t)(r0 + 8) * HID + c) =
                    __floats2half2_rn(acc[i][j][2] + sBias[c], acc[i][j][3] + sBias[c + 1]);
        }
    }
}

// ---------------------------------------------------------------------------
// Kernel 2: fused edge pipeline (R14 structure).
//   t = relu(h@W1a + ef@W1e + b1') ; m = t@W2 + b2 ; scatter via red.v2.
// 256 threads, 2 CTAs/SM, 64x32 warp tiles, 5 streamed K=64 chunks.
// smem: sH (h then t) | sEF | B0 | B1 | misc = 91648 B
// ---------------------------------------------------------------------------
static constexpr int SH_B  = 0;
static constexpr int EF_B  = 34816;
static constexpr int B0_B  = EF_B + 128 * EF_STR;      // 53248
static constexpr int B1_B  = B0_B + 128 * SB_STR;      // 71680
static constexpr int MISC_B = B1_B + 128 * SB_STR;     // 90112
static constexpr int EDGE_SMEM = MISC_B + 3 * 128 * 4; // 91648

__global__ __launch_bounds__(256, 2) void k_edge(const int* __restrict__ eidx,
                                                 const float* __restrict__ ef,
                                                 const float* __restrict__ b2) {
    char* smem = dyn_smem;
    float* sB1p = reinterpret_cast<float*>(smem + MISC_B);
    float* sB2b = sB1p + 128;
    int* sDst = reinterpret_cast<int*>(sB2b + 128);
    const uint32_t sb0 = smem_u32(smem);

    const int tid = threadIdx.x, lane = tid & 31, w = tid >> 5;
    const int e0 = blockIdx.x * 128;

    if (tid < 128) {
        sDst[tid] = eidx[NE + e0 + tid];
        sB1p[tid] = g_b1p[tid];
    } else {
        sB2b[tid - 128] = b2[tid - 128];
    }

    // g0: gather h[src] -> sH
#pragma unroll
    for (int i = tid; i < 128 * 16; i += 256) {
        int r = i >> 4, s = i & 15;
        int src = eidx[e0 + r];
        CP16(sb0 + SH_B + (uint32_t)(r * SA_STR + s * 16),
             g_h + (size_t)src * HID + s * 8);
    }
    CP_COMMIT();
    // g1: c1 = W1a[:,0:64] -> B0
    stage_chunk256(sb0 + B0_B, g_W1t, 256, tid);
    CP_COMMIT();
    // g2: c2 = W1a[:,64:128] -> B1
    stage_chunk256(sb0 + B1_B, g_W1t + 64, 256, tid);
    CP_COMMIT();

    // ef [128x64] fp32 -> fp16 into sEF
#pragma unroll
    for (int i = tid; i < 128 * 16; i += 256) {
        int r = i >> 4, c = (i & 15) * 4;
        float4 v = *reinterpret_cast<const float4*>(ef + (size_t)(e0 + r) * 64 + c);
        __half2* p = reinterpret_cast<__half2*>(smem + EF_B + r * EF_STR + c * 2);
        p[0] = __floats2half2_rn(v.x, v.y);
        p[1] = __floats2half2_rn(v.z, v.w);
    }

    // warp tiling: 2 (M) x 4 (N) warps, 64x32 each
    const int mb = (w & 1) * 64, nb = (w >> 1) * 32;
    uint32_t aH[4], aF[4];
#pragma unroll
    for (int m = 0; m < 4; ++m) {
        aH[m] = sb0 + SH_B + (uint32_t)(mb + m * 16) * SA_STR + a_off(lane, SA_STR);
        aF[m] = sb0 + EF_B + (uint32_t)(mb + m * 16) * EF_STR + a_off(lane, EF_STR);
    }
    uint32_t b0A[2], b1A[2];
#pragma unroll
    for (int jj = 0; jj < 2; ++jj) {
        uint32_t off = (uint32_t)(nb + jj * 16) * SB_STR + b_off(lane, SB_STR);
        b0A[jj] = sb0 + B0_B + off;
        b1A[jj] = sb0 + B1_B + off;
    }

    const int g = lane >> 2, tg = lane & 3;
    float acc[4][4][4];

    // ---- GEMM1: t_acc = h@W1a + ef@W1e  (3 K=64 chunks) ----
    CP_WAIT(1);          // g0 (gather) + g1 (c1) complete
    __syncthreads();     // publish sH, c1, ef, biases
    zacc64(acc);
    wgemm64<4>(aH, b0A, acc);                       // c1: h k0:64

    CP_WAIT(0);          // c2 complete
    __syncthreads();     // publish c2; B0 free
    stage_chunk256(sb0 + B0_B, g_W1et, 64, tid);    // c3 = W1e -> B0
    CP_COMMIT();
    {
        uint32_t aH2[4] = {aH[0] + 128, aH[1] + 128, aH[2] + 128, aH[3] + 128};
        wgemm64<4>(aH2, b1A, acc);                  // c2: h k64:128
    }
    CP_WAIT(0);
    __syncthreads();     // publish c3; B1 free; all h reads done
    stage_chunk256(sb0 + B1_B, g_W2t, 128, tid);    // c4 = W2[:,0:64] -> B1
    CP_COMMIT();
    wgemm64<4>(aF, b0A, acc);                       // c3: ef @ W1e (K=64)
    CP_WAIT(0);
    __syncthreads();     // publish c4; B0 free
    stage_chunk256(sb0 + B0_B, g_W2t + 64, 128, tid);  // c5 = W2[:,64:128] -> B0
    CP_COMMIT();

    // epilogue: t = relu(acc + b1') -> sH (h fully consumed at c2)
#pragma unroll
    for (int m = 0; m < 4; ++m) {
        int r0 = mb + m * 16 + g;
#pragma unroll
        for (int j = 0; j < 4; ++j) {
            int c = nb + j * 8 + 2 * tg;
            *reinterpret_cast<__half2*>(smem + SH_B + r0 * SA_STR + c * 2) =
                __floats2half2_rn(fmaxf(acc[m][j][0] + sB1p[c], 0.f),
                                  fmaxf(acc[m][j][1] + sB1p[c + 1], 0.f));
            *reinterpret_cast<__half2*>(smem + SH_B + (r0 + 8) * SA_STR + c * 2) =
                __floats2half2_rn(fmaxf(acc[m][j][2] + sB1p[c], 0.f),
                                  fmaxf(acc[m][j][3] + sB1p[c + 1], 0.f));
        }
    }
    __syncthreads();     // publish t

    // ---- GEMM2: m = t @ W2 (K=128) ----
    zacc64(acc);
    wgemm64<4>(aH, b1A, acc);                       // c4: t k0:64
    CP_WAIT(0);
    __syncthreads();     // publish c5
    {
        uint32_t aH2[4] = {aH[0] + 128, aH[1] + 128, aH[2] + 128, aH[3] + 128};
        wgemm64<4>(aH2, b0A, acc);                  // c5: t k64:128
    }

    // scatter via vectored reductions (red.global.add.v2.f32)
#pragma unroll
    for (int m = 0; m < 4; ++m) {
        int r0 = mb + m * 16 + g;
        float* p0 = g_agg + (size_t)sDst[r0] * HID;
        float* p1 = g_agg + (size_t)sDst[r0 + 8] * HID;
#pragma unroll
        for (int j = 0; j < 4; ++j) {
            int c = nb + j * 8 + 2 * tg;
            RED_V2(p0 + c, acc[m][j][0] + sB2b[c], acc[m][j][1] + sB2b[c + 1]);
            RED_V2(p1 + c, acc[m][j][2] + sB2b[c], acc[m][j][3] + sB2b[c + 1]);
        }
    }
}

// ---------------------------------------------------------------------------
// Kernel 3: out = relu([nf|agg] @ U1 + ub1) @ U2 + ub2
// 256 threads, 2 CTAs/SM, 64x32 warp tiles, 6 streamed K=64 chunks.
// ---------------------------------------------------------------------------
static constexpr int UNF_B = 0;
static constexpr int UAG_B = 34816;
static constexpr int UB0_B = UAG_B + 128 * SA_STR;     // 69632
static constexpr int UB1_B = UB0_B + 128 * SB_STR;     // 88064
static constexpr int UMISC_B = UB1_B + 128 * SB_STR;   // 106496
static constexpr int UPD_SMEM = UMISC_B + 2 * 128 * 4; // 107520

__global__ __launch_bounds__(256, 2) void k_update(const float* __restrict__ nf,
                                                   const float* __restrict__ b1,
                                                   const float* __restrict__ b2,
                                                   float* __restrict__ out) {
    char* smem = dyn_smem;
    float* sB1 = reinterpret_cast<float*>(smem + UMISC_B);
    float* sB2 = sB1 + 128;
    const uint32_t sb0 = smem_u32(smem);

    const int tid = threadIdx.x, lane = tid & 31, w = tid >> 5;
    const int base = blockIdx.x * 128;

    if (tid < 128) sB1[tid] = b1[tid];
    else sB2[tid - 128] = b2[tid - 128];

    stage_chunk256(sb0 + UB0_B, g_U1t, 256, tid);
    CP_COMMIT();
    stage_chunk256(sb0 + UB1_B, g_U1t + 64, 256, tid);
    CP_COMMIT();

    for (int i = tid; i < 128 * 32; i += 256) {
        int r = i >> 5, c = (i & 31) * 4;
        int gr = base + r;
        float4 v0 = make_float4(0.f, 0.f, 0.f, 0.f), v1 = v0;
        if (gr < NN) {
            v0 = *reinterpret_cast<const float4*>(nf + (size_t)gr * HID + c);
            v1 = *reinterpret_cast<const float4*>(g_agg + (size_t)gr * HID + c);
        }
        __half2* p0 = reinterpret_cast<__half2*>(smem + UNF_B + r * SA_STR + c * 2);
        p0[0] = __floats2half2_rn(v0.x, v0.y);
        p0[1] = __floats2half2_rn(v0.z, v0.w);
        __half2* p1 = reinterpret_cast<__half2*>(smem + UAG_B + r * SA_STR + c * 2);
        p1[0] = __floats2half2_rn(v1.x, v1.y);
        p1[1] = __floats2half2_rn(v1.z, v1.w);
    }

    const int mb = (w & 1) * 64, nb = (w >> 1) * 32;
    uint32_t aN[4], aN2[4], aG[4], aG2[4];
#pragma unroll
    for (int m = 0; m < 4; ++m) {
        aN[m] = sb0 + UNF_B + (uint32_t)(mb + m * 16) * SA_STR + a_off(lane, SA_STR);
        aN2[m] = aN[m] + 128;
        aG[m] = sb0 + UAG_B + (uint32_t)(mb + m * 16) * SA_STR + a_off(lane, SA_STR);
        aG2[m] = aG[m] + 128;
    }
    uint32_t b0A[2], b1A[2];
#pragma unroll
    for (int jj = 0; jj < 2; ++jj) {
        uint32_t off = (uint32_t)(nb + jj * 16) * SB_STR + b_off(lane, SB_STR);
        b0A[jj] = sb0 + UB0_B + off;
        b1A[jj] = sb0 + UB1_B + off;
    }

    const int g = lane >> 2, tg = lane & 3;
    float acc[4][4][4];

    CP_WAIT(0);
    __syncthreads();     // publish u1, u2, A tiles, biases
    zacc64(acc);
    wgemm64<4>(aN, b0A, acc);                       // u1: nf k0:64
    __syncthreads();     // B0 consumed by all (WAR)
    stage_chunk256(sb0 + UB0_B, g_U1t + 128, 256, tid);  // u3 -> B0
    CP_COMMIT();
    wgemm64<4>(aN2, b1A, acc);                      // u2: nf k64:128
    CP_WAIT(0);
    __syncthreads();     // publish u3; B1 free
    stage_chunk256(sb0 + UB1_B, g_U1t + 192, 256, tid);  // u4 -> B1
    CP_COMMIT();
    wgemm64<4>(aG, b0A, acc);                       // u3: agg k0:64
    CP_WAIT(0);
    __syncthreads();     // publish u4; B0 free
    stage_chunk256(sb0 + UB0_B, g_U2t, 128, tid);   // u5 = U2[:,0:64] -> B0
    CP_COMMIT();
    wgemm64<4>(aG2, b1A, acc);                      // u4: agg k64:128
    CP_WAIT(0);
    __syncthreads();     // publish u5; B1 free
    stage_chunk256(sb0 + UB1_B, g_U2t + 64, 128, tid);  // u6 -> B1
    CP_COMMIT();

    // epilogue: t = relu(acc + b1) -> sNF
#pragma unroll
    for (int m = 0; m < 4; ++m) {
        int r0 = mb + m * 16 + g;
#pragma unroll
        for (int j = 0; j < 4; ++j) {
            int c = nb + j * 8 + 2 * tg;
            *reinterpret_cast<__half2*>(smem + UNF_B + r0 * SA_STR + c * 2) =
                __floats2half2_rn(fmaxf(acc[m][j][0] + sB1[c], 0.f),
                                  fmaxf(acc[m][j][1] + sB1[c + 1], 0.f));
            *reinterpret_cast<__half2*>(smem + UNF_B + (r0 + 8) * SA_STR + c * 2) =
                __floats2half2_rn(fmaxf(acc[m][j][2] + sB1[c], 0.f),
                                  fmaxf(acc[m][j][3] + sB1[c + 1], 0.f));
        }
    }
    CP_WAIT(0);          // u6 landed
    __syncthreads();     // publish t + u6

    zacc64(acc);
    wgemm64<4>(aN, b0A, acc);                       // u5
    wgemm64<4>(aN2, b1A, acc);                      // u6

#pragma unroll
    for (int m = 0; m < 4; ++m) {
        int r0 = base + mb + m * 16 + g;
#pragma unroll
        for (int j = 0; j < 4; ++j) {
            int c = nb + j * 8 + 2 * tg;
            if (r0 < NN)
                *reinterpret_cast<float2*>(out + (size_t)r0 * HID + c) =
                    make_float2(acc[m][j][0] + sB2[c], acc[m][j][1] + sB2[c + 1]);
            if (r0 + 8 < NN)
                *reinterpret_cast<float2*>(out + (size_t)(r0 + 8) * HID + c) =
                    make_float2(acc[m][j][2] + sB2[c], acc[m][j][3] + sB2[c + 1]);
        }
    }
}

// ---------------------------------------------------------------------------
extern "C" void kernel_launch(void* const* d_in, const int* in_sizes, int n_in,
                              void* d_out, int out_size) {
    const float* node_feats = (const float*)d_in[0];
    const int*   edge_idx   = (const int*)d_in[1];
    const float* edge_feats = (const float*)d_in[2];
    const float* node_W     = (const float*)d_in[3];
    const float* node_b     = (const float*)d_in[4];
    const float* edge_W     = (const float*)d_in[5];
    const float* edge_b     = (const float*)d_in[6];
    const float* msg_W1     = (const float*)d_in[7];
    const float* msg_b1     = (const float*)d_in[8];
    const float* msg_W2     = (const float*)d_in[9];
    const float* msg_b2     = (const float*)d_in[10];
    const float* upd_W1     = (const float*)d_in[11];
    const float* upd_b1     = (const float*)d_in[12];
    const float* upd_W2     = (const float*)d_in[13];
    const float* upd_b2     = (const float*)d_in[14];
    float* out = (float*)d_out;

    cudaFuncSetAttribute(k_node,   cudaFuncAttributeMaxDynamicSharedMemorySize, NODE_SMEM);
    cudaFuncSetAttribute(k_edge,   cudaFuncAttributeMaxDynamicSharedMemorySize, EDGE_SMEM);
    cudaFuncSetAttribute(k_update, cudaFuncAttributeMaxDynamicSharedMemorySize, UPD_SMEM);

    const int NB_NODE = (NN + 127) / 128;  // 391
    const int NB_EDGE = NE / 128;          // 6250

    k_tW<<<128, 256>>>(node_W, edge_W, edge_b, msg_W1, msg_b1, msg_W2,
                       upd_W1, upd_W2);
    k_node<<<NB_NODE, 512, NODE_SMEM>>>(node_feats, node_b);
    k_edge<<<NB_EDGE, 256, EDGE_SMEM>>>(edge_idx, edge_feats, msg_b2);
    k_update<<<NB_NODE, 256, UPD_SMEM>>>(node_feats, upd_b1, upd_b2, out);
}

// round 17
// speedup vs baseline: 1.1402x; 1.0684x over previous
#include <cuda_runtime.h>
#include <cuda_fp16.h>
#include <cstdint>

#define HID 128
#define NN 50000
#define NE 800000
// byte strides (all ≡16 mod 128 -> ldmatrix conflict-free)
#define SA_STR 272   // A tiles rows: 136 halves
#define EF_STR 144   // ef tile rows: 72 halves
#define SB_STR 144   // B K=64 chunk buffers

extern __shared__ char dyn_smem[];

// ---------------- device scratch (allocation-free rule) ----------------
__device__ __half g_h[(size_t)NN * HID];
__device__ float  g_agg[(size_t)NN * HID];
__device__ __half g_nWt[128 * 128];
__device__ __half g_W1t[128 * 256];   // msg_W1^T [n][k]
__device__ __half g_W1et[128 * 64];   // (eW @ W1b)^T [n][kf]  (fused)
__device__ float  g_b1p[128];         // b1 + eb @ W1b
__device__ __half g_W2t[128 * 128];
__device__ __half g_U1t[128 * 256];
__device__ __half g_U2t[128 * 128];

// ======================= helpers (generic PTX) =========================
__device__ __forceinline__ uint32_t smem_u32(const void* p) {
    uint32_t a;
    asm("{ .reg .u64 t; cvta.to.shared.u64 t, %1; cvt.u32.u64 %0, t; }"
        : "=r"(a) : "l"(p));
    return a;
}
__device__ __forceinline__ void ldsm4(uint32_t r[4], uint32_t addr) {
    asm volatile("ldmatrix.sync.aligned.m8n8.x4.shared.b16 {%0,%1,%2,%3}, [%4];"
                 : "=r"(r[0]), "=r"(r[1]), "=r"(r[2]), "=r"(r[3]) : "r"(addr));
}
__device__ __forceinline__ void mma16(float c[4], const uint32_t a[4],
                                      uint32_t b0, uint32_t b1) {
    asm volatile("mma.sync.aligned.m16n8k16.row.col.f32.f16.f16.f32 "
                 "{%0,%1,%2,%3}, {%4,%5,%6,%7}, {%8,%9}, {%0,%1,%2,%3};"
                 : "+f"(c[0]), "+f"(c[1]), "+f"(c[2]), "+f"(c[3])
                 : "r"(a[0]), "r"(a[1]), "r"(a[2]), "r"(a[3]), "r"(b0), "r"(b1));
}
#define CP16(dst, src) \
    asm volatile("cp.async.cg.shared.global [%0], [%1], 16;" :: "r"(dst), "l"(src))
#define CP_COMMIT() asm volatile("cp.async.commit_group;" ::: "memory")
#define CP_WAIT(n)  asm volatile("cp.async.wait_group %0;" :: "n"(n) : "memory")
// vectored global reductions (sm_90 base PTX)
#define RED_V2(gptr, x, y) \
    asm volatile("red.global.add.v2.f32 [%0], {%1, %2};" \
                 :: "l"(gptr), "f"(x), "f"(y) : "memory")
#define RED_V4(gptr, x, y, z, u) \
    asm volatile("red.global.add.v4.f32 [%0], {%1, %2, %3, %4};" \
                 :: "l"(gptr), "f"(x), "f"(y), "f"(z), "f"(u) : "memory")

__device__ __forceinline__ uint32_t a_off(int lane, int strideB) {
    int row = (lane & 7) + ((lane & 8) ? 8 : 0);
    return (uint32_t)row * strideB + ((lane & 16) ? 16 : 0);
}
__device__ __forceinline__ uint32_t b_off(int lane, int strideB) {
    int row = (lane & 7) + ((lane & 16) ? 8 : 0);
    return (uint32_t)row * strideB + ((lane & 8) ? 16 : 0);
}

// ---- 64x32 warp GEMM (4 m16-tiles x 4 n8-cols) ----
__device__ __forceinline__ void zacc64(float acc[4][4][4]) {
#pragma unroll
    for (int m = 0; m < 4; ++m)
#pragma unroll
        for (int j = 0; j < 4; ++j)
#pragma unroll
            for (int k = 0; k < 4; ++k) acc[m][j][k] = 0.f;
}
template <int KSTEPS>
__device__ __forceinline__ void wgemm64(const uint32_t aA[4], const uint32_t bA[2],
                                        float acc[4][4][4]) {
#pragma unroll
    for (int ks = 0; ks < KSTEPS; ++ks) {
        uint32_t b0[4], b1[4];
        ldsm4(b0, bA[0] + ks * 32);
        ldsm4(b1, bA[1] + ks * 32);
#pragma unroll
        for (int m = 0; m < 4; ++m) {
            uint32_t a[4];
            ldsm4(a, aA[m] + ks * 32);
            mma16(acc[m][0], a, b0[0], b0[1]);
            mma16(acc[m][1], a, b0[2], b0[3]);
            mma16(acc[m][2], a, b1[0], b1[1]);
            mma16(acc[m][3], a, b1[2], b1[3]);
        }
    }
}

// ---- 32x32 warp GEMM (k_node @512 thr) ----
__device__ __forceinline__ void zacc(float acc[2][4][4]) {
#pragma unroll
    for (int i = 0; i < 2; ++i)
#pragma unroll
        for (int j = 0; j < 4; ++j)
#pragma unroll
            for (int k = 0; k < 4; ++k) acc[i][j][k] = 0.f;
}
template <int KSTEPS>
__device__ __forceinline__ void wgemm(uint32_t aA0, uint32_t aA1,
                                      const uint32_t bA[2], float acc[2][4][4]) {
#pragma unroll
    for (int ks = 0; ks < KSTEPS; ++ks) {
        uint32_t a0[4], a1[4];
        ldsm4(a0, aA0 + ks * 32);
        ldsm4(a1, aA1 + ks * 32);
#pragma unroll
        for (int jj = 0; jj < 2; ++jj) {
            uint32_t b[4];
            ldsm4(b, bA[jj] + ks * 32);
            mma16(acc[0][2 * jj],     a0, b[0], b[1]);
            mma16(acc[0][2 * jj + 1], a0, b[2], b[3]);
            mma16(acc[1][2 * jj],     a1, b[0], b[1]);
            mma16(acc[1][2 * jj + 1], a1, b[2], b[3]);
        }
    }
}

__device__ __forceinline__ void stage_chunk256(uint32_t dstB, const __half* srcBase,
                                               int srcK, int tid) {
#pragma unroll
    for (int i = tid; i < 128 * 8; i += 256) {
        int n = i >> 3, k8 = (i & 7) * 8;
        CP16(dstB + (uint32_t)(n * SB_STR + k8 * 2),
             srcBase + (size_t)n * srcK + k8);
    }
}

// ---------------------------------------------------------------------------
// Prep: transposes + fp16 + the eW@W1b fusion
// ---------------------------------------------------------------------------
__global__ void k_tW(const float* __restrict__ nW, const float* __restrict__ eW,
                     const float* __restrict__ eb, const float* __restrict__ W1,
                     const float* __restrict__ b1, const float* __restrict__ W2,
                     const float* __restrict__ U1, const float* __restrict__ U2) {
    int t = blockIdx.x * blockDim.x + threadIdx.x;
    int tot = gridDim.x * blockDim.x;
    for (int i = t; i < 128 * 128; i += tot) {
        int n = i >> 7, k = i & 127;
        g_nWt[i] = __float2half_rn(nW[k * 128 + n]);
        g_W2t[i] = __float2half_rn(W2[k * 128 + n]);
        g_U2t[i] = __float2half_rn(U2[k * 128 + n]);
    }
    for (int i = t; i < 128 * 256; i += tot) {
        int n = i >> 8, k = i & 255;
        g_W1t[i] = __float2half_rn(W1[k * 128 + n]);
        g_U1t[i] = __float2half_rn(U1[k * 128 + n]);
    }
    for (int i = t; i < 128 * 64; i += tot) {
        int n = i >> 6, kf = i & 63;
        float s = 0.f;
#pragma unroll 4
        for (int j = 0; j < 128; ++j)
            s = fmaf(eW[kf * 128 + j], W1[(128 + j) * 128 + n], s);
        g_W1et[i] = __float2half_rn(s);
    }
    for (int i = t; i < 128; i += tot) {
        float s = b1[i];
#pragma unroll 4
        for (int j = 0; j < 128; ++j)
            s = fmaf(eb[j], W1[(128 + j) * 128 + i], s);
        g_b1p[i] = s;
    }
}

// ---------------------------------------------------------------------------
// Kernel 1: h = fp16(node_feats @ node_W + node_b) -> g_h; also zeroes g_agg
// ---------------------------------------------------------------------------
static constexpr int NODE_SA = 0;
static constexpr int NODE_SB = 128 * SA_STR;
static constexpr int NODE_BIAS = NODE_SB + 128 * SA_STR;
static constexpr int NODE_SMEM = NODE_BIAS + 512;

__global__ __launch_bounds__(512, 2) void k_node(const float* __restrict__ nf,
                                                 const float* __restrict__ b) {
    char* smem = dyn_smem;
    float* sBias = reinterpret_cast<float*>(smem + NODE_BIAS);
    const uint32_t sb0 = smem_u32(smem);
    const int tid = threadIdx.x, lane = tid & 31, w = tid >> 5;
    const int base = blockIdx.x * 128;

    if (tid < 128) sBias[tid] = b[tid];
    // zero g_agg rows owned by this block (fused k_zero_agg)
    for (int i = tid; i < 128 * 32; i += 512) {
        int r = i >> 5, c = (i & 31) * 4;
        int gr = base + r;
        if (gr < NN)
            *reinterpret_cast<float4*>(g_agg + (size_t)gr * HID + c) =
                make_float4(0.f, 0.f, 0.f, 0.f);
    }
    for (int i = tid; i < 128 * 32; i += 512) {
        int r = i >> 5, c = (i & 31) * 4;
        int gr = base + r;
        float4 v = make_float4(0.f, 0.f, 0.f, 0.f);
        if (gr < NN) v = *reinterpret_cast<const float4*>(nf + (size_t)gr * HID + c);
        __half2* p = reinterpret_cast<__half2*>(smem + NODE_SA + r * SA_STR + c * 2);
        p[0] = __floats2half2_rn(v.x, v.y);
        p[1] = __floats2half2_rn(v.z, v.w);
    }
    for (int i = tid; i < 128 * 16; i += 512) {
        int r = i >> 4, s = (i & 15);
        *reinterpret_cast<float4*>(smem + NODE_SB + r * SA_STR + s * 16) =
            *reinterpret_cast<const float4*>(
                reinterpret_cast<const char*>(g_nWt) + (size_t)r * 256 + s * 16);
    }
    __syncthreads();

    const int mb = (w & 3) * 32, nb = (w >> 2) * 32;
    uint32_t aA0 = sb0 + NODE_SA + (uint32_t)mb * SA_STR + a_off(lane, SA_STR);
    uint32_t aA1 = aA0 + 16 * SA_STR;
    uint32_t bA[2];
#pragma unroll
    for (int jj = 0; jj < 2; ++jj)
        bA[jj] = sb0 + NODE_SB + (uint32_t)(nb + jj * 16) * SA_STR + b_off(lane, SA_STR);

    float acc[2][4][4];
    zacc(acc);
    wgemm<8>(aA0, aA1, bA, acc);

    const int g = lane >> 2, tg = lane & 3;
#pragma unroll
    for (int i = 0; i < 2; ++i) {
        int r0 = base + mb + i * 16 + g;
#pragma unroll
        for (int j = 0; j < 4; ++j) {
            int c = nb + j * 8 + 2 * tg;
            if (r0 < NN)
                *reinterpret_cast<__half2*>(g_h + (size_t)r0 * HID + c) =
                    __floats2half2_rn(acc[i][j][0] + sBias[c], acc[i][j][1] + sBias[c + 1]);
            if (r0 + 8 < NN)
                *reinterpret_cast<__half2*>(g_h + (size_t)(r0 + 8) * HID + c) =
                    __floats2half2_rn(acc[i][j][2] + sBias[c], acc[i][j][3] + sBias[c + 1]);
        }
    }
}

// ---------------------------------------------------------------------------
// Kernel 2: fused edge pipeline.
//   t = relu(h@W1a + ef@W1e + b1') ; m = t@W2 + b2 ; scatter via red.v4.
// 256 threads, 2 CTAs/SM, 64x32 warp tiles, 5 streamed K=64 chunks.
// ---------------------------------------------------------------------------
static constexpr int SH_B  = 0;
static constexpr int EF_B  = 34816;
static constexpr int B0_B  = EF_B + 128 * EF_STR;      // 53248
static constexpr int B1_B  = B0_B + 128 * SB_STR;      // 71680
static constexpr int MISC_B = B1_B + 128 * SB_STR;     // 90112
static constexpr int EDGE_SMEM = MISC_B + 3 * 128 * 4; // 91648

__global__ __launch_bounds__(256, 2) void k_edge(const int* __restrict__ eidx,
                                                 const float* __restrict__ ef,
                                                 const float* __restrict__ b2) {
    char* smem = dyn_smem;
    float* sB1p = reinterpret_cast<float*>(smem + MISC_B);
    float* sB2b = sB1p + 128;
    int* sDst = reinterpret_cast<int*>(sB2b + 128);
    const uint32_t sb0 = smem_u32(smem);

    const int tid = threadIdx.x, lane = tid & 31, w = tid >> 5;
    const int e0 = blockIdx.x * 128;

    if (tid < 128) {
        sDst[tid] = eidx[NE + e0 + tid];
        sB1p[tid] = g_b1p[tid];
    } else {
        sB2b[tid - 128] = b2[tid - 128];
    }

    // g0: gather h[src] -> sH
#pragma unroll
    for (int i = tid; i < 128 * 16; i += 256) {
        int r = i >> 4, s = i & 15;
        int src = eidx[e0 + r];
        CP16(sb0 + SH_B + (uint32_t)(r * SA_STR + s * 16),
             g_h + (size_t)src * HID + s * 8);
    }
    CP_COMMIT();
    // g1: c1 = W1a[:,0:64] -> B0
    stage_chunk256(sb0 + B0_B, g_W1t, 256, tid);
    CP_COMMIT();
    // g2: c2 = W1a[:,64:128] -> B1
    stage_chunk256(sb0 + B1_B, g_W1t + 64, 256, tid);
    CP_COMMIT();

    // ef [128x64] fp32 -> fp16 into sEF
#pragma unroll
    for (int i = tid; i < 128 * 16; i += 256) {
        int r = i >> 4, c = (i & 15) * 4;
        float4 v = *reinterpret_cast<const float4*>(ef + (size_t)(e0 + r) * 64 + c);
        __half2* p = reinterpret_cast<__half2*>(smem + EF_B + r * EF_STR + c * 2);
        p[0] = __floats2half2_rn(v.x, v.y);
        p[1] = __floats2half2_rn(v.z, v.w);
    }

    // warp tiling: 2 (M) x 4 (N) warps, 64x32 each
    const int mb = (w & 1) * 64, nb = (w >> 1) * 32;
    uint32_t aH[4], aF[4];
#pragma unroll
    for (int m = 0; m < 4; ++m) {
        aH[m] = sb0 + SH_B + (uint32_t)(mb + m * 16) * SA_STR + a_off(lane, SA_STR);
        aF[m] = sb0 + EF_B + (uint32_t)(mb + m * 16) * EF_STR + a_off(lane, EF_STR);
    }
    uint32_t b0A[2], b1A[2];
#pragma unroll
    for (int jj = 0; jj < 2; ++jj) {
        uint32_t off = (uint32_t)(nb + jj * 16) * SB_STR + b_off(lane, SB_STR);
        b0A[jj] = sb0 + B0_B + off;
        b1A[jj] = sb0 + B1_B + off;
    }

    const int g = lane >> 2, tg = lane & 3;
    float acc[4][4][4];

    // ---- GEMM1: t_acc = h@W1a + ef@W1e  (3 K=64 chunks) ----
    CP_WAIT(1);          // g0 (gather) + g1 (c1) complete
    __syncthreads();     // publish sH, c1, ef, biases
    zacc64(acc);
    wgemm64<4>(aH, b0A, acc);                       // c1: h k0:64

    CP_WAIT(0);          // c2 complete
    __syncthreads();     // publish c2; B0 free
    stage_chunk256(sb0 + B0_B, g_W1et, 64, tid);    // c3 = W1e -> B0
    CP_COMMIT();
    {
        uint32_t aH2[4] = {aH[0] + 128, aH[1] + 128, aH[2] + 128, aH[3] + 128};
        wgemm64<4>(aH2, b1A, acc);                  // c2: h k64:128
    }
    CP_WAIT(0);
    __syncthreads();     // publish c3; B1 free; all h reads done
    stage_chunk256(sb0 + B1_B, g_W2t, 128, tid);    // c4 = W2[:,0:64] -> B1
    CP_COMMIT();
    wgemm64<4>(aF, b0A, acc);                       // c3: ef @ W1e (K=64)
    CP_WAIT(0);
    __syncthreads();     // publish c4; B0 free
    stage_chunk256(sb0 + B0_B, g_W2t + 64, 128, tid);  // c5 = W2[:,64:128] -> B0
    CP_COMMIT();

    // epilogue: t = relu(acc + b1') -> sH (h fully consumed at c2)
#pragma unroll
    for (int m = 0; m < 4; ++m) {
        int r0 = mb + m * 16 + g;
#pragma unroll
        for (int j = 0; j < 4; ++j) {
            int c = nb + j * 8 + 2 * tg;
            *reinterpret_cast<__half2*>(smem + SH_B + r0 * SA_STR + c * 2) =
                __floats2half2_rn(fmaxf(acc[m][j][0] + sB1p[c], 0.f),
                                  fmaxf(acc[m][j][1] + sB1p[c + 1], 0.f));
            *reinterpret_cast<__half2*>(smem + SH_B + (r0 + 8) * SA_STR + c * 2) =
                __floats2half2_rn(fmaxf(acc[m][j][2] + sB1p[c], 0.f),
                                  fmaxf(acc[m][j][3] + sB1p[c + 1], 0.f));
        }
    }
    __syncthreads();     // publish t

    // ---- GEMM2: m = t @ W2 (K=128) ----
    zacc64(acc);
    wgemm64<4>(aH, b1A, acc);                       // c4: t k0:64
    CP_WAIT(0);
    __syncthreads();     // publish c5
    {
        uint32_t aH2[4] = {aH[0] + 128, aH[1] + 128, aH[2] + 128, aH[3] + 128};
        wgemm64<4>(aH2, b0A, acc);                  // c5: t k64:128
    }

    // scatter: pair even/odd tg lanes via shfl -> red.global.add.v4.f32
    // lane = g*4 + tg; lane+1 holds columns c+2, c+3 of the same rows.
#pragma unroll
    for (int m = 0; m < 4; ++m) {
        int r0 = mb + m * 16 + g;
        float* p0 = g_agg + (size_t)sDst[r0] * HID;
        float* p1 = g_agg + (size_t)sDst[r0 + 8] * HID;
#pragma unroll
        for (int j = 0; j < 4; ++j) {
            int c = nb + j * 8 + 2 * tg;
            float v0 = acc[m][j][0] + sB2b[c];
            float v1 = acc[m][j][1] + sB2b[c + 1];
            float v2 = acc[m][j][2] + sB2b[c];
            float v3 = acc[m][j][3] + sB2b[c + 1];
            float u0 = __shfl_down_sync(0xFFFFFFFFu, v0, 1);
            float u1 = __shfl_down_sync(0xFFFFFFFFu, v1, 1);
            float u2 = __shfl_down_sync(0xFFFFFFFFu, v2, 1);
            float u3 = __shfl_down_sync(0xFFFFFFFFu, v3, 1);
            if (!(tg & 1)) {
                RED_V4(p0 + c, v0, v1, u0, u1);
                RED_V4(p1 + c, v2, v3, u2, u3);
            }
        }
    }
}

// ---------------------------------------------------------------------------
// Kernel 3: out = relu([nf|agg] @ U1 + ub1) @ U2 + ub2
// 256 threads, 2 CTAs/SM, 64x32 warp tiles, 6 streamed K=64 chunks.
// ---------------------------------------------------------------------------
static constexpr int UNF_B = 0;
static constexpr int UAG_B = 34816;
static constexpr int UB0_B = UAG_B + 128 * SA_STR;     // 69632
static constexpr int UB1_B = UB0_B + 128 * SB_STR;     // 88064
static constexpr int UMISC_B = UB1_B + 128 * SB_STR;   // 106496
static constexpr int UPD_SMEM = UMISC_B + 2 * 128 * 4; // 107520

__global__ __launch_bounds__(256, 2) void k_update(const float* __restrict__ nf,
                                                   const float* __restrict__ b1,
                                                   const float* __restrict__ b2,
                                                   float* __restrict__ out) {
    char* smem = dyn_smem;
    float* sB1 = reinterpret_cast<float*>(smem + UMISC_B);
    float* sB2 = sB1 + 128;
    const uint32_t sb0 = smem_u32(smem);

    const int tid = threadIdx.x, lane = tid & 31, w = tid >> 5;
    const int base = blockIdx.x * 128;

    if (tid < 128) sB1[tid] = b1[tid];
    else sB2[tid - 128] = b2[tid - 128];

    stage_chunk256(sb0 + UB0_B, g_U1t, 256, tid);
    CP_COMMIT();
    stage_chunk256(sb0 + UB1_B, g_U1t + 64, 256, tid);
    CP_COMMIT();

    for (int i = tid; i < 128 * 32; i += 256) {
        int r = i >> 5, c = (i & 31) * 4;
        int gr = base + r;
        float4 v0 = make_float4(0.f, 0.f, 0.f, 0.f), v1 = v0;
        if (gr < NN) {
            v0 = *reinterpret_cast<const float4*>(nf + (size_t)gr * HID + c);
            v1 = *reinterpret_cast<const float4*>(g_agg + (size_t)gr * HID + c);
        }
        __half2* p0 = reinterpret_cast<__half2*>(smem + UNF_B + r * SA_STR + c * 2);
        p0[0] = __floats2half2_rn(v0.x, v0.y);
        p0[1] = __floats2half2_rn(v0.z, v0.w);
        __half2* p1 = reinterpret_cast<__half2*>(smem + UAG_B + r * SA_STR + c * 2);
        p1[0] = __floats2half2_rn(v1.x, v1.y);
        p1[1] = __floats2half2_rn(v1.z, v1.w);
    }

    const int mb = (w & 1) * 64, nb = (w >> 1) * 32;
    uint32_t aN[4], aN2[4], aG[4], aG2[4];
#pragma unroll
    for (int m = 0; m < 4; ++m) {
        aN[m] = sb0 + UNF_B + (uint32_t)(mb + m * 16) * SA_STR + a_off(lane, SA_STR);
        aN2[m] = aN[m] + 128;
        aG[m] = sb0 + UAG_B + (uint32_t)(mb + m * 16) * SA_STR + a_off(lane, SA_STR);
        aG2[m] = aG[m] + 128;
    }
    uint32_t b0A[2], b1A[2];
#pragma unroll
    for (int jj = 0; jj < 2; ++jj) {
        uint32_t off = (uint32_t)(nb + jj * 16) * SB_STR + b_off(lane, SB_STR);
        b0A[jj] = sb0 + UB0_B + off;
        b1A[jj] = sb0 + UB1_B + off;
    }

    const int g = lane >> 2, tg = lane & 3;
    float acc[4][4][4];

    CP_WAIT(0);
    __syncthreads();     // publish u1, u2, A tiles, biases
    zacc64(acc);
    wgemm64<4>(aN, b0A, acc);                       // u1: nf k0:64
    __syncthreads();     // B0 consumed by all (WAR)
    stage_chunk256(sb0 + UB0_B, g_U1t + 128, 256, tid);  // u3 -> B0
    CP_COMMIT();
    wgemm64<4>(aN2, b1A, acc);                      // u2: nf k64:128
    CP_WAIT(0);
    __syncthreads();     // publish u3; B1 free
    stage_chunk256(sb0 + UB1_B, g_U1t + 192, 256, tid);  // u4 -> B1
    CP_COMMIT();
    wgemm64<4>(aG, b0A, acc);                       // u3: agg k0:64
    CP_WAIT(0);
    __syncthreads();     // publish u4; B0 free
    stage_chunk256(sb0 + UB0_B, g_U2t, 128, tid);   // u5 = U2[:,0:64] -> B0
    CP_COMMIT();
    wgemm64<4>(aG2, b1A, acc);                      // u4: agg k64:128
    CP_WAIT(0);
    __syncthreads();     // publish u5; B1 free
    stage_chunk256(sb0 + UB1_B, g_U2t + 64, 128, tid);  // u6 -> B1
    CP_COMMIT();

    // epilogue: t = relu(acc + b1) -> sNF
#pragma unroll
    for (int m = 0; m < 4; ++m) {
        int r0 = mb + m * 16 + g;
#pragma unroll
        for (int j = 0; j < 4; ++j) {
            int c = nb + j * 8 + 2 * tg;
            *reinterpret_cast<__half2*>(smem + UNF_B + r0 * SA_STR + c * 2) =
                __floats2half2_rn(fmaxf(acc[m][j][0] + sB1[c], 0.f),
                                  fmaxf(acc[m][j][1] + sB1[c + 1], 0.f));
            *reinterpret_cast<__half2*>(smem + UNF_B + (r0 + 8) * SA_STR + c * 2) =
                __floats2half2_rn(fmaxf(acc[m][j][2] + sB1[c], 0.f),
                                  fmaxf(acc[m][j][3] + sB1[c + 1], 0.f));
        }
    }
    CP_WAIT(0);          // u6 landed
    __syncthreads();     // publish t + u6

    zacc64(acc);
    wgemm64<4>(aN, b0A, acc);                       // u5
    wgemm64<4>(aN2, b1A, acc);                      // u6

#pragma unroll
    for (int m = 0; m < 4; ++m) {
        int r0 = base + mb + m * 16 + g;
#pragma unroll
        for (int j = 0; j < 4; ++j) {
            int c = nb + j * 8 + 2 * tg;
            if (r0 < NN)
                *reinterpret_cast<float2*>(out + (size_t)r0 * HID + c) =
                    make_float2(acc[m][j][0] + sB2[c], acc[m][j][1] + sB2[c + 1]);
            if (r0 + 8 < NN)
                *reinterpret_cast<float2*>(out + (size_t)(r0 + 8) * HID + c) =
                    make_float2(acc[m][j][2] + sB2[c], acc[m][j][3] + sB2[c + 1]);
        }
    }
}

// ---------------------------------------------------------------------------
extern "C" void kernel_launch(void* const* d_in, const int* in_sizes, int n_in,
                              void* d_out, int out_size) {
    const float* node_feats = (const float*)d_in[0];
    const int*   edge_idx   = (const int*)d_in[1];
    const float* edge_feats = (const float*)d_in[2];
    const float* node_W     = (const float*)d_in[3];
    const float* node_b     = (const float*)d_in[4];
    const float* edge_W     = (const float*)d_in[5];
    const float* edge_b     = (const float*)d_in[6];
    const float* msg_W1     = (const float*)d_in[7];
    const float* msg_b1     = (const float*)d_in[8];
    const float* msg_W2     = (const float*)d_in[9];
    const float* msg_b2     = (const float*)d_in[10];
    const float* upd_W1     = (const float*)d_in[11];
    const float* upd_b1     = (const float*)d_in[12];
    const float* upd_W2     = (const float*)d_in[13];
    const float* upd_b2     = (const float*)d_in[14];
    float* out = (float*)d_out;

    cudaFuncSetAttribute(k_node,   cudaFuncAttributeMaxDynamicSharedMemorySize, NODE_SMEM);
    cudaFuncSetAttribute(k_edge,   cudaFuncAttributeMaxDynamicSharedMemorySize, EDGE_SMEM);
    cudaFuncSetAttribute(k_update, cudaFuncAttributeMaxDynamicSharedMemorySize, UPD_SMEM);

    const int NB_NODE = (NN + 127) / 128;  // 391
    const int NB_EDGE = NE / 128;          // 6250

    k_tW<<<128, 256>>>(node_W, edge_W, edge_b, msg_W1, msg_b1, msg_W2,
                       upd_W1, upd_W2);
    k_node<<<NB_NODE, 512, NODE_SMEM>>>(node_feats, node_b);
    k_edge<<<NB_EDGE, 256, EDGE_SMEM>>>(edge_idx, edge_feats, msg_b2);
    k_update<<<NB_NODE, 256, UPD_SMEM>>>(node_feats, upd_b1, upd_b2, out);
}